// round 5
// baseline (speedup 1.0000x reference)
#include <cuda_runtime.h>

// ---------------------------------------------------------------------------
// LDPC damped sum-product BP decoder, GB300.
//   N_VAR=8192 variables, N_CHK=4096 checks, DV=3 (edges grouped by variable:
//   edge e = 3*v + j), BATCH=128, T=30 iterations.
//
// Math (per iteration):
//   var:  vs[v]   = sum_j C2V[3v+j]
//         v2c     = chn[v] + vs[v] - C2V[e]
//         V2C[e]  = g*v2c + (1-g)*V2C[e]          (g = sigmoid(gamma_logit))
//         t       = tanh(clip(V2C,-15,15)/2)      -> f[e] = sign(t)*max(|t|,eps)
//   chk:  P[c]    = prod_{e in c} f[e]            (signed product == parity)
//         ext     = clip(P/f[e], -1+eps, 1-eps)
//         C2V[e]  = log((1+ext)/(1-ext))          (= 2*atanh)
//   out[t][v] = chn[v] + sum_j C2V_new[3v+j]      (fused into next var kernel)
//
// Product-domain check update replaces the reference's log-domain exclusion;
// they differ only when message magnitudes are <~1e-35 (absolute error there
// is immaterial vs the 1e-3 relative tolerance on O(1) posteriors).
// ---------------------------------------------------------------------------

#define NVAR  8192
#define NCHK  4096
#define DVV   3
#define NE    (NVAR * DVV)      // 24576
#define BB    128
#define TITER 30
#define EPSV  1e-7f

// Scratch state (no allocation allowed -> __device__ globals).
__device__ float g_msgC2V[NE * BB];   // check -> variable messages
__device__ float g_msgV2C[NE * BB];   // variable -> check messages (damped)
__device__ float g_ta[NE * BB];       // signed clamped tanh values f[e]
__device__ int   g_cnt[NCHK];
__device__ int   g_off[NCHK + 1];
__device__ int   g_cur[NCHK];
__device__ int   g_edges[NE];         // edge ids sorted by check (CSR payload)

// ---------------------------------------------------------------------------
// CSR build for the check side (rebuilt every launch; ~10us total).
// ---------------------------------------------------------------------------
__global__ void zero_cnt_k() {
    int i = blockIdx.x * blockDim.x + threadIdx.x;
    if (i < NCHK) g_cnt[i] = 0;
}

__global__ void hist_k(const int* __restrict__ echk) {
    int e = blockIdx.x * blockDim.x + threadIdx.x;
    if (e < NE) atomicAdd(&g_cnt[echk[e]], 1);
}

// Single-block exclusive scan over 4096 counts (4 per thread, 1024 threads).
__global__ void scan_k() {
    __shared__ int sh[1024];
    int t = threadIdx.x;
    int c0 = g_cnt[4 * t + 0];
    int c1 = g_cnt[4 * t + 1];
    int c2 = g_cnt[4 * t + 2];
    int c3 = g_cnt[4 * t + 3];
    int s  = c0 + c1 + c2 + c3;
    sh[t] = s;
    __syncthreads();
    for (int off = 1; off < 1024; off <<= 1) {
        int v = (t >= off) ? sh[t - off] : 0;
        __syncthreads();
        sh[t] += v;
        __syncthreads();
    }
    int excl = sh[t] - s;   // exclusive prefix for this thread's 4 slots
    int o = excl;
    g_off[4 * t + 0] = o; g_cur[4 * t + 0] = o; o += c0;
    g_off[4 * t + 1] = o; g_cur[4 * t + 1] = o; o += c1;
    g_off[4 * t + 2] = o; g_cur[4 * t + 2] = o; o += c2;
    g_off[4 * t + 3] = o; g_cur[4 * t + 3] = o; o += c3;
    if (t == 1023) g_off[NCHK] = o;   // == NE
}

__global__ void scat_k(const int* __restrict__ echk) {
    int e = blockIdx.x * blockDim.x + threadIdx.x;
    if (e < NE) {
        int p = atomicAdd(&g_cur[echk[e]], 1);
        g_edges[p] = e;
    }
}

// ---------------------------------------------------------------------------
// Variable-side kernel. Handles 4 variables per block; threadIdx.x = batch.
// FIRST: messages are all zero (iteration 0), skip loads and the output write.
// Otherwise also emits the PREVIOUS iteration's posterior (chn + sum C2V),
// which it needs to read anyway.
// ---------------------------------------------------------------------------
template <bool FIRST>
__global__ void __launch_bounds__(512) var_k(const float* __restrict__ chn,
                                             const float* __restrict__ gl,
                                             float* __restrict__ outp) {
    int v = blockIdx.x * 4 + threadIdx.y;
    int b = threadIdx.x;
    float g = 1.0f / (1.0f + __expf(-gl[0]));   // sigmoid (broadcast load)
    int base = v * DVV;

    float c0 = 0.0f, c1 = 0.0f, c2 = 0.0f;
    if (!FIRST) {
        c0 = g_msgC2V[(base + 0) * BB + b];
        c1 = g_msgC2V[(base + 1) * BB + b];
        c2 = g_msgC2V[(base + 2) * BB + b];
    }
    float ch = chn[v * BB + b];
    float vs = c0 + c1 + c2;
    if (!FIRST) outp[v * BB + b] = ch + vs;     // posterior of prev iteration

#pragma unroll
    for (int j = 0; j < DVV; j++) {
        float cj  = (j == 0) ? c0 : ((j == 1) ? c1 : c2);
        int   idx = (base + j) * BB + b;
        float vn  = ch + vs - cj;                       // extrinsic v->c
        float old = FIRST ? 0.0f : g_msgV2C[idx];
        float nv  = g * vn + (1.0f - g) * old;          // damping
        g_msgV2C[idx] = nv;

        float x   = fminf(fmaxf(nv, -15.0f), 15.0f);
        float ax  = fabsf(x);
        float e   = __expf(-ax);                        // tanh(|x|/2) = (1-e)/(1+e)
        float mag = __fdividef(1.0f - e, 1.0f + e);
        float ta  = fmaxf(mag, EPSV);
        g_ta[idx] = (x < 0.0f) ? -ta : ta;              // sign matches (t < 0)
    }
}

// ---------------------------------------------------------------------------
// Check-side kernel. 2 checks per block; threadIdx.x = batch.
// Pass 1: signed product over the check's edges (sign bit carries parity).
// Pass 2: extrinsic = P / f_e (re-read hits L1), then 2*atanh.
// ---------------------------------------------------------------------------
__global__ void __launch_bounds__(256) chk_k() {
    int c = blockIdx.x * 2 + threadIdx.y;
    int b = threadIdx.x;
    int s  = g_off[c];
    int en = g_off[c + 1];

    float P = 1.0f;
    for (int i = s; i < en; i++) {
        int eid = g_edges[i];                 // uniform across the warp
        P *= g_ta[eid * BB + b];
    }
    for (int i = s; i < en; i++) {
        int   eid = g_edges[i];
        float f   = g_ta[eid * BB + b];       // L1 hit
        float ext = __fdividef(P, f);
        ext = fminf(fmaxf(ext, -1.0f + EPSV), 1.0f - EPSV);
        float msg = __logf(__fdividef(1.0f + ext, 1.0f - ext));  // 2*atanh
        g_msgC2V[eid * BB + b] = msg;
    }
}

// Final posterior for iteration T-1.
__global__ void __launch_bounds__(512) out_k(const float* __restrict__ chn,
                                             float* __restrict__ outp) {
    int v = blockIdx.x * 4 + threadIdx.y;
    int b = threadIdx.x;
    int base = v * DVV;
    float s = g_msgC2V[(base + 0) * BB + b]
            + g_msgC2V[(base + 1) * BB + b]
            + g_msgC2V[(base + 2) * BB + b];
    outp[v * BB + b] = chn[v * BB + b] + s;
}

// ---------------------------------------------------------------------------
extern "C" void kernel_launch(void* const* d_in, const int* in_sizes, int n_in,
                              void* d_out, int out_size) {
    (void)in_sizes; (void)n_in; (void)out_size;
    const float* chn  = (const float*)d_in[0];   // (8192, 128) f32
    const float* gl   = (const float*)d_in[1];   // (1,)        f32
    const int*   evar = (const int*)d_in[2];     // structured: e/3 (unused)
    const int*   echk = (const int*)d_in[3];     // (24576,)    i32
    (void)evar;
    float* out = (float*)d_out;                  // (30, 8192, 128) f32

    // Build check-side CSR (per launch, deterministic work).
    zero_cnt_k<<<(NCHK + 255) / 256, 256>>>();
    hist_k    <<<(NE   + 255) / 256, 256>>>(echk);
    scan_k    <<<1, 1024>>>();
    scat_k    <<<(NE   + 255) / 256, 256>>>(echk);

    dim3 vb(BB, 4), vg(NVAR / 4);    // 512 thr, 2048 blocks
    dim3 cb(BB, 2), cg(NCHK / 2);    // 256 thr, 2048 blocks

    var_k<true><<<vg, vb>>>(chn, gl, nullptr);
    chk_k<<<cg, cb>>>();
    for (int t = 1; t < TITER; t++) {
        var_k<false><<<vg, vb>>>(chn, gl, out + (size_t)(t - 1) * NVAR * BB);
        chk_k<<<cg, cb>>>();
    }
    out_k<<<vg, vb>>>(chn, out + (size_t)(TITER - 1) * NVAR * BB);
}